// round 9
// baseline (speedup 1.0000x reference)
#include <cuda_runtime.h>

#define N_V   2048
#define N_E   1024
#define N_MOL 64
#define V_DIM 128
#define E_DIM 64
#define H_DIM 32
#define FEAT  (2*V_DIM + E_DIM)   // 320
#define CAP   256                 // per-molecule member capacity (avg 32)
#define GRID  296                 // 2 blocks/SM on 148 SMs — all co-resident
#define NRELA 128                 // blocks [0,128) also run a rela unit

// Scratch (static device globals — allocation-free per harness rules)
__device__ int      g_src[N_E];
__device__ int      g_dst[N_E];
__device__ float    g_rela[N_V * 3];
__device__ unsigned g_bar = 0;     // self-resetting grid barrier counter

// ---------------------------------------------------------------------------
// Fast accurate softplus: softplus(x) = x/2 + ln2 + ln cosh(x/2).
// |x|<1: 5-term even Taylor of ln cosh (abs err < 4e-7 at boundary) — FMA
// pipe only. Exact path for |x|>=1 (rare; inputs have sigma ~0.13).
// ---------------------------------------------------------------------------
__device__ __forceinline__ float softplus_fast(float x) {
    float ax = fabsf(x);
    if (ax < 1.0f) {
        float t = 0.5f * x;
        float u = t * t;
        float p = 2.1869489e-3f;
        p = fmaf(p, u, -6.7460317e-3f);
        p = fmaf(p, u,  2.2222222e-2f);
        p = fmaf(p, u, -8.3333333e-2f);
        p = fmaf(p, u,  0.5f);
        return fmaf(u, p, t + 0.69314718056f);
    }
    return fmaxf(x, 0.f) + log1pf(__expf(-ax));
}

// decode one float4 of the one-hot pair at float4-index idx
__device__ __forceinline__ void recover_one(const float4& a, const float4& b,
                                            int idx) {
    const int i = idx >> 8;            // vertex (row)
    const int j = (idx & 255) << 2;    // edge base (col)
    if (a.x != 0.f) g_src[j + 0] = i;
    if (a.y != 0.f) g_src[j + 1] = i;
    if (a.z != 0.f) g_src[j + 2] = i;
    if (a.w != 0.f) g_src[j + 3] = i;
    if (b.x != 0.f) g_dst[j + 0] = i;
    if (b.y != 0.f) g_dst[j + 1] = i;
    if (b.z != 0.f) g_dst[j + 2] = i;
    if (b.w != 0.f) g_dst[j + 3] = i;
}

// ---------------------------------------------------------------------------
// Fused kernel: phase1 (recover stream + rela) | grid barrier | phase2 (bond)
// ---------------------------------------------------------------------------
__global__ void __launch_bounds__(256, 2)
fused_kernel(const float4* __restrict__ vew1,
             const float4* __restrict__ vew2,
             const float*  __restrict__ mvw,
             const float*  __restrict__ m,
             const float*  __restrict__ q,
             const float*  __restrict__ Wr,
             const float*  __restrict__ br,
             const float*  __restrict__ v,
             const float*  __restrict__ e,
             const float*  __restrict__ W1,
             const float*  __restrict__ W2,
             const float*  __restrict__ b2,
             float*        __restrict__ out) {
    __shared__ float sW1[H_DIM * FEAT];            // 40 KB (phase 2)
    __shared__ int   midx[CAP];
    __shared__ float sqx[CAP], sqy[CAP], sqz[CAP], smm[CAP];
    __shared__ float sWr0[H_DIM], sWr1[H_DIM], sWr2[H_DIM], sbr[H_DIM];
    __shared__ int   swsum[8], swoff[8], ssize;

    const int tid  = threadIdx.x;
    const int lane = tid & 31;
    const int wl   = tid >> 5;
    const int bid  = blockIdx.x;

    // ======================= PHASE 1 =======================
    if (bid < NRELA) {
        // ---- smaller recover share: 6 float4-pairs ----
        const int gt = bid * 256 + tid;            // [0, 32768)
        #pragma unroll
        for (int k = 0; k < 6; k++) {
            const int idx = k * 32768 + gt;        // covers [0, 196608)
            recover_one(vew1[idx], vew2[idx], idx);
        }

        // ---- rela unit: molecule bid>>1, member parity bid&1 ----
        const int mo  = bid >> 1;
        const int par = bid & 1;
        if (tid < H_DIM) {
            sWr0[tid] = Wr[3*tid + 0];
            sWr1[tid] = Wr[3*tid + 1];
            sWr2[tid] = Wr[3*tid + 2];
            sbr[tid]  = br[tid];
        }

        // single-pass scan compaction: thread owns 8 consecutive columns
        const float4* mrow4 = (const float4*)(mvw + mo * N_V);
        float4 v0 = mrow4[2*tid], v1 = mrow4[2*tid + 1];
        unsigned m8 = 0;
        if (v0.x != 0.f) m8 |= 1u;   if (v0.y != 0.f) m8 |= 2u;
        if (v0.z != 0.f) m8 |= 4u;   if (v0.w != 0.f) m8 |= 8u;
        if (v1.x != 0.f) m8 |= 16u;  if (v1.y != 0.f) m8 |= 32u;
        if (v1.z != 0.f) m8 |= 64u;  if (v1.w != 0.f) m8 |= 128u;
        const int c = __popc(m8);
        int incl = c;
        #pragma unroll
        for (int o = 1; o < 32; o <<= 1) {
            int n = __shfl_up_sync(0xffffffffu, incl, o);
            if (lane >= o) incl += n;
        }
        if (lane == 31) swsum[wl] = incl;
        __syncthreads();
        if (tid == 0) {
            int run = 0;
            #pragma unroll
            for (int w8 = 0; w8 < 8; w8++) { swoff[w8] = run; run += swsum[w8]; }
            ssize = run;
        }
        __syncthreads();
        int pos = swoff[wl] + (incl - c);
        #pragma unroll
        for (int k = 0; k < 8; k++) {
            if (m8 & (1u << k)) {
                const int i = tid * 8 + k;
                if (pos < CAP) {
                    midx[pos] = i;
                    sqx[pos] = q[3*i + 0];
                    sqy[pos] = q[3*i + 1];
                    sqz[pos] = q[3*i + 2];
                    smm[pos] = m[i];
                }
                pos++;
            }
        }
        __syncthreads();
        int size = ssize;
        if (size > CAP) size = CAP;

        // warp-per-member over this parity half
        for (int s = par + 2 * wl; s < size; s += 16) {
            const float qix = sqx[s], qiy = sqy[s], qiz = sqz[s], mi = smm[s];
            float a0 = 0.f, a1 = 0.f, a2 = 0.f;
            for (int t = lane; t < size; t += 32) {
                float d0 = qix - sqx[t];
                float d1 = qiy - sqy[t];
                float d2 = qiz - sqz[t];
                float n2 = fmaf(d0, d0, fmaf(d1, d1, d2 * d2));
                if (n2 > 0.f) {
                    float ss2 = 0.f;
                    #pragma unroll
                    for (int h = 0; h < H_DIM; h++) {
                        float x = fmaf(sWr0[h], d0,
                                  fmaf(sWr1[h], d1,
                                  fmaf(sWr2[h], d2, sbr[h])));
                        float sp = softplus_fast(x);
                        ss2 = fmaf(sp, sp, ss2);
                    }
                    float y = rsqrtf(ss2);                 // 1/delta_d
                    float cc = (y * y - y) * mi * smm[t] * rsqrtf(n2);
                    a0 = fmaf(d0, cc, a0);
                    a1 = fmaf(d1, cc, a1);
                    a2 = fmaf(d2, cc, a2);
                }
            }
            #pragma unroll
            for (int o = 16; o; o >>= 1) {
                a0 += __shfl_xor_sync(0xffffffffu, a0, o);
                a1 += __shfl_xor_sync(0xffffffffu, a1, o);
                a2 += __shfl_xor_sync(0xffffffffu, a2, o);
            }
            if (lane == 0) {
                const int i = midx[s];       // one writer per vertex
                g_rela[3*i + 0] = a0;
                g_rela[3*i + 1] = a1;
                g_rela[3*i + 2] = a2;
            }
        }
    } else {
        // ---- larger recover share: up to 8 float4-pairs ----
        const int gt = (bid - NRELA) * 256 + tid;  // [0, 43008)
        #pragma unroll 4
        for (int k = 0; k < 8; k++) {
            const int idx = 196608 + k * 43008 + gt;   // covers rest
            if (idx < (N_V * N_E) / 4)
                recover_one(vew1[idx], vew2[idx], idx);
        }
    }

    // ======================= GRID BARRIER =======================
    __threadfence();                 // publish g_src/g_dst/g_rela (all threads)
    __syncthreads();
    if (tid == 0) {
        unsigned t = atomicAdd(&g_bar, 1u);
        if (t == gridDim.x - 1) {
            atomicExch(&g_bar, 0u);              // release (self-reset)
        } else {
            while (atomicAdd(&g_bar, 0u) != 0u) __nanosleep(32);
        }
    }
    __syncthreads();
    __threadfence();                 // acquire

    // ======================= PHASE 2: bond + combine =======================
    for (int t = tid; t < (H_DIM * FEAT) / 4; t += 256)
        ((float4*)sW1)[t] = ((const float4*)W1)[t];
    __syncthreads();

    const int gw = bid * 8 + wl;                  // 2368 warps >= 2048 units
    if (gw >= 2 * N_E) return;
    const int er = (gw < N_E) ? gw : gw - N_E;
    int u, w;
    if (gw < N_E) { u = g_src[er]; w = g_dst[er]; }
    else          { u = g_dst[er]; w = g_src[er]; }

    const float* __restrict__ vu = v + u * V_DIM;
    const float* __restrict__ vw = v + w * V_DIM;
    const float* __restrict__ ee = e + er * E_DIM;

    float f[10];
    #pragma unroll
    for (int k = 0; k < 4; k++) f[k] = vu[32 * k + lane];
    f[4] = ee[lane];
    f[5] = ee[32 + lane];
    #pragma unroll
    for (int k = 0; k < 4; k++) f[6 + k] = vw[32 * k + lane];

    float acc[32];
    #pragma unroll
    for (int t = 0; t < 32; t++) acc[t] = 0.f;
    #pragma unroll
    for (int k = 0; k < 10; k++) {
        const float* __restrict__ Wp = sW1 + 32 * k + lane;  // conflict-free
        const float fk = f[k];
        #pragma unroll
        for (int t = 0; t < 32; t++)
            acc[t] = fmaf(fk, Wp[t * FEAT], acc[t]);
    }

    // log-compaction butterfly: ends with acc[0] = h[lane]
    #pragma unroll
    for (int s = 0; s < 5; s++) {
        const int o = 1 << s;
        const int n = 16 >> s;
        #pragma unroll
        for (int k = 0; k < 16; k++) {
            if (k < n) {
                float give = (lane & o) ? acc[2*k]     : acc[2*k + 1];
                float keep = (lane & o) ? acc[2*k + 1] : acc[2*k];
                acc[k] = keep + __shfl_xor_sync(0xffffffffu, give, o);
            }
        }
    }
    float h = fmaxf(acc[0], 0.f);

    float val = h * W2[lane];
    #pragma unroll
    for (int o = 16; o; o >>= 1) val += __shfl_xor_sync(0xffffffffu, val, o);

    if (lane == 0) {
        val += b2[0];
        float d0 = q[3*u + 0] - q[3*w + 0];
        float d1 = q[3*u + 1] - q[3*w + 1];
        float d2 = q[3*u + 2] - q[3*w + 2];
        float s = rsqrtf(fmaf(d0, d0, fmaf(d1, d1, d2 * d2))) * val;
        out[3*gw + 0] = fmaf(d0, s, g_rela[3*gw + 0]);
        out[3*gw + 1] = fmaf(d1, s, g_rela[3*gw + 1]);
        out[3*gw + 2] = fmaf(d2, s, g_rela[3*gw + 2]);
    }
}

// ---------------------------------------------------------------------------
extern "C" void kernel_launch(void* const* d_in, const int* in_sizes, int n_in,
                              void* d_out, int out_size) {
    const float* v    = (const float*)d_in[0];
    const float* e    = (const float*)d_in[1];
    const float* m    = (const float*)d_in[2];
    const float* q    = (const float*)d_in[3];
    const float* vew1 = (const float*)d_in[4];
    const float* vew2 = (const float*)d_in[5];
    const float* mvw  = (const float*)d_in[6];
    const float* W1   = (const float*)d_in[7];
    const float* W2   = (const float*)d_in[8];
    const float* b2   = (const float*)d_in[9];
    const float* Wr   = (const float*)d_in[10];
    const float* br   = (const float*)d_in[11];
    float* out = (float*)d_out;

    fused_kernel<<<GRID, 256>>>((const float4*)vew1, (const float4*)vew2,
                                mvw, m, q, Wr, br,
                                v, e, W1, W2, b2, out);
}

// round 10
// speedup vs baseline: 1.1290x; 1.1290x over previous
#include <cuda_runtime.h>

#define N_V   2048
#define N_E   1024
#define N_MOL 64
#define V_DIM 128
#define E_DIM 64
#define H_DIM 32
#define FEAT  (2*V_DIM + E_DIM)   // 320
#define CAP   256                 // per-molecule member capacity (avg 32)
#define NRELA 128                 // K1 blocks [0,NRELA) run rela units

// Scratch (static device globals — allocation-free per harness rules)
__device__ int   g_src[N_E];
__device__ int   g_dst[N_E];
__device__ float g_rela[N_V * 3];

// ---------------------------------------------------------------------------
// Fast accurate softplus: softplus(x) = x/2 + ln2 + ln cosh(x/2).
// |x|<1: 5-term even Taylor of ln cosh (abs err < 4e-7 at boundary) — FMA
// pipe only. Exact path for |x|>=1 (rare; inputs have sigma ~0.13).
// ---------------------------------------------------------------------------
__device__ __forceinline__ float softplus_fast(float x) {
    float ax = fabsf(x);
    if (ax < 1.0f) {
        float t = 0.5f * x;
        float u = t * t;
        float p = 2.1869489e-3f;
        p = fmaf(p, u, -6.7460317e-3f);
        p = fmaf(p, u,  2.2222222e-2f);
        p = fmaf(p, u, -8.3333333e-2f);
        p = fmaf(p, u,  0.5f);
        return fmaf(u, p, t + 0.69314718056f);
    }
    return fmaxf(x, 0.f) + log1pf(__expf(-ax));
}

// ---------------------------------------------------------------------------
// K1: heterogeneous, non-interacting halves.
//   blocks [0,128):   rela forces -> g_rela (self-compacts from mvw)
//   blocks [128,640): recover src/dst from vew1/vew2 (R8-proven pattern)
// ---------------------------------------------------------------------------
__global__ void k1_kernel(const float4* __restrict__ vew1,
                          const float4* __restrict__ vew2,
                          const float*  __restrict__ mvw,
                          const float*  __restrict__ m,
                          const float*  __restrict__ q,
                          const float*  __restrict__ Wr,
                          const float*  __restrict__ br) {
    const int tid  = threadIdx.x;
    const int lane = tid & 31;
    const int wl   = tid >> 5;

    if (blockIdx.x >= NRELA) {
        // ---- recover: 512 blocks x 256 threads, 4 float4 per matrix each ----
        const int gtid = (blockIdx.x - NRELA) * 256 + tid;   // [0, 131072)
        float4 a[4], b[4];
        #pragma unroll
        for (int r = 0; r < 4; r++) a[r] = vew1[r * 131072 + gtid];
        #pragma unroll
        for (int r = 0; r < 4; r++) b[r] = vew2[r * 131072 + gtid];
        #pragma unroll
        for (int r = 0; r < 4; r++) {
            const int idx = r * 131072 + gtid;
            const int i = idx >> 8;            // row (vertex)
            const int j = (idx & 255) << 2;    // edge base
            if (a[r].x != 0.f) g_src[j + 0] = i;
            if (a[r].y != 0.f) g_src[j + 1] = i;
            if (a[r].z != 0.f) g_src[j + 2] = i;
            if (a[r].w != 0.f) g_src[j + 3] = i;
            if (b[r].x != 0.f) g_dst[j + 0] = i;
            if (b[r].y != 0.f) g_dst[j + 1] = i;
            if (b[r].z != 0.f) g_dst[j + 2] = i;
            if (b[r].w != 0.f) g_dst[j + 3] = i;
        }
        return;
    }

    // ---- rela: 2 blocks per molecule (parity-split members) ----
    __shared__ int   midx[CAP];
    __shared__ float sqx[CAP], sqy[CAP], sqz[CAP], smm[CAP];
    __shared__ float sWr0[H_DIM], sWr1[H_DIM], sWr2[H_DIM], sbr[H_DIM];
    __shared__ int   wcnt[8];
    __shared__ int   s_base;

    const int mo  = blockIdx.x >> 1;
    const int par = blockIdx.x & 1;

    if (tid < H_DIM) {
        sWr0[tid] = Wr[3*tid + 0];
        sWr1[tid] = Wr[3*tid + 1];
        sWr2[tid] = Wr[3*tid + 2];
        sbr[tid]  = br[tid];
    }
    if (tid == 0) s_base = 0;
    __syncthreads();

    // deterministic ordered compaction of this molecule's members from mvw row
    const float* __restrict__ mrow = mvw + mo * N_V;
    for (int base = 0; base < N_V; base += 256) {
        const int t = base + tid;
        const bool hit = (mrow[t] != 0.f);
        const unsigned msk = __ballot_sync(0xffffffffu, hit);
        if (lane == 0) wcnt[wl] = __popc(msk);
        __syncthreads();
        int woff = s_base;
        #pragma unroll
        for (int j = 0; j < 8; j++) if (j < wl) woff += wcnt[j];
        if (hit) {
            int p = woff + __popc(msk & ((1u << lane) - 1u));
            if (p < CAP) {
                midx[p] = t;
                sqx[p] = q[3*t + 0];
                sqy[p] = q[3*t + 1];
                sqz[p] = q[3*t + 2];
                smm[p] = m[t];
            }
        }
        __syncthreads();
        if (tid == 0) {
            int s = 0;
            #pragma unroll
            for (int j = 0; j < 8; j++) s += wcnt[j];
            s_base += s;
        }
        __syncthreads();
    }
    int size = s_base;
    if (size > CAP) size = CAP;

    // warp-per-member; this block handles members with index parity `par`
    for (int s = par + 2 * wl; s < size; s += 16) {
        const float qix = sqx[s], qiy = sqy[s], qiz = sqz[s], mi = smm[s];
        float a0 = 0.f, a1 = 0.f, a2 = 0.f;
        for (int t = lane; t < size; t += 32) {
            float d0 = qix - sqx[t];
            float d1 = qiy - sqy[t];
            float d2 = qiz - sqz[t];
            float n2 = fmaf(d0, d0, fmaf(d1, d1, d2 * d2));
            if (n2 > 0.f) {
                float ss = 0.f;
                #pragma unroll
                for (int h = 0; h < H_DIM; h++) {
                    float x = fmaf(sWr0[h], d0,
                              fmaf(sWr1[h], d1,
                              fmaf(sWr2[h], d2, sbr[h])));
                    float sp = softplus_fast(x);
                    ss = fmaf(sp, sp, ss);
                }
                float y = rsqrtf(ss);                   // 1/delta_d
                float c = (y * y - y) * mi * smm[t] * rsqrtf(n2);
                a0 = fmaf(d0, c, a0);
                a1 = fmaf(d1, c, a1);
                a2 = fmaf(d2, c, a2);
            }
        }
        #pragma unroll
        for (int o = 16; o; o >>= 1) {
            a0 += __shfl_xor_sync(0xffffffffu, a0, o);
            a1 += __shfl_xor_sync(0xffffffffu, a1, o);
            a2 += __shfl_xor_sync(0xffffffffu, a2, o);
        }
        if (lane == 0) {
            const int i = midx[s];          // each vertex written exactly once
            g_rela[3*i + 0] = a0;
            g_rela[3*i + 1] = a1;
            g_rela[3*i + 2] = a2;
        }
    }
}

// ---------------------------------------------------------------------------
// K2: bond forces + combine. One warp per EDGE er, computing BOTH output rows
// er (u->w) and er+N_E (w->u): the features are the same 10 chunks with the
// v-halves swapped, so every W1 value read from smem feeds 2 FMAs (halves the
// smem-crossbar bytes that dominated the old version). Butterfly reduce twice;
// out[k] = f_bond[k] + g_rela[k].
// ---------------------------------------------------------------------------
__global__ void __launch_bounds__(256, 2)
bond_kernel(const float* __restrict__ v,
            const float* __restrict__ e,
            const float* __restrict__ q,
            const float* __restrict__ W1,
            const float* __restrict__ W2,
            const float* __restrict__ b2,
            float* __restrict__ out) {
    __shared__ float sW1[H_DIM * FEAT];               // 40 KB, [t][c]
    const int tid = threadIdx.x;
    for (int t = tid; t < (H_DIM * FEAT) / 4; t += 256)
        ((float4*)sW1)[t] = ((const float4*)W1)[t];
    __syncthreads();

    const int lane = tid & 31;
    const int wl   = tid >> 5;
    const int er   = blockIdx.x * 8 + wl;             // 128 blocks * 8 = 1024
    const int u = g_src[er];
    const int w = g_dst[er];

    const float* __restrict__ vu = v + u * V_DIM;
    const float* __restrict__ vw = v + w * V_DIM;
    const float* __restrict__ ee = e + er * E_DIM;

    // shared feature chunks (coalesced)
    float fu[4], fw[4], fe[2];
    #pragma unroll
    for (int k = 0; k < 4; k++) fu[k] = vu[32 * k + lane];
    fe[0] = ee[lane];
    fe[1] = ee[32 + lane];
    #pragma unroll
    for (int k = 0; k < 4; k++) fw[k] = vw[32 * k + lane];

    float accf[32], accr[32];
    #pragma unroll
    for (int t = 0; t < 32; t++) { accf[t] = 0.f; accr[t] = 0.f; }

    #pragma unroll
    for (int k = 0; k < 10; k++) {
        const float* __restrict__ Wp = sW1 + 32 * k + lane;  // conflict-free
        const float ff = (k < 4) ? fu[k] : (k < 6) ? fe[k - 4] : fw[k - 6];
        const float fr = (k < 4) ? fw[k] : (k < 6) ? fe[k - 4] : fu[k - 6];
        #pragma unroll
        for (int t = 0; t < 32; t++) {
            const float wv = Wp[t * FEAT];
            accf[t] = fmaf(ff, wv, accf[t]);
            accr[t] = fmaf(fr, wv, accr[t]);
        }
    }

    // log-compaction butterfly (x2): ends with acc[0] = h[lane]
    #pragma unroll
    for (int s = 0; s < 5; s++) {
        const int o = 1 << s;
        const int n = 16 >> s;
        #pragma unroll
        for (int k = 0; k < 16; k++) {
            if (k < n) {
                float gf = (lane & o) ? accf[2*k]     : accf[2*k + 1];
                float kf = (lane & o) ? accf[2*k + 1] : accf[2*k];
                accf[k] = kf + __shfl_xor_sync(0xffffffffu, gf, o);
                float gr = (lane & o) ? accr[2*k]     : accr[2*k + 1];
                float kr = (lane & o) ? accr[2*k + 1] : accr[2*k];
                accr[k] = kr + __shfl_xor_sync(0xffffffffu, gr, o);
            }
        }
    }
    const float w2l = W2[lane];
    float vf = fmaxf(accf[0], 0.f) * w2l;
    float vr = fmaxf(accr[0], 0.f) * w2l;
    #pragma unroll
    for (int o = 16; o; o >>= 1) {
        vf += __shfl_xor_sync(0xffffffffu, vf, o);
        vr += __shfl_xor_sync(0xffffffffu, vr, o);
    }

    if (lane == 0) {
        const float bb = b2[0];
        vf += bb;
        vr += bb;
        float d0 = q[3*u + 0] - q[3*w + 0];
        float d1 = q[3*u + 1] - q[3*w + 1];
        float d2 = q[3*u + 2] - q[3*w + 2];
        float inv = rsqrtf(fmaf(d0, d0, fmaf(d1, d1, d2 * d2)));
        float sf = inv * vf;
        float sr = inv * vr;
        const int kf = er;              // row using dq = q[u]-q[w]
        const int kr = er + N_E;        // row using dq = q[w]-q[u]
        out[3*kf + 0] = fmaf(d0,  sf, g_rela[3*kf + 0]);
        out[3*kf + 1] = fmaf(d1,  sf, g_rela[3*kf + 1]);
        out[3*kf + 2] = fmaf(d2,  sf, g_rela[3*kf + 2]);
        out[3*kr + 0] = fmaf(-d0, sr, g_rela[3*kr + 0]);
        out[3*kr + 1] = fmaf(-d1, sr, g_rela[3*kr + 1]);
        out[3*kr + 2] = fmaf(-d2, sr, g_rela[3*kr + 2]);
    }
}

// ---------------------------------------------------------------------------
extern "C" void kernel_launch(void* const* d_in, const int* in_sizes, int n_in,
                              void* d_out, int out_size) {
    const float* v    = (const float*)d_in[0];
    const float* e    = (const float*)d_in[1];
    const float* m    = (const float*)d_in[2];
    const float* q    = (const float*)d_in[3];
    const float* vew1 = (const float*)d_in[4];
    const float* vew2 = (const float*)d_in[5];
    const float* mvw  = (const float*)d_in[6];
    const float* W1   = (const float*)d_in[7];
    const float* W2   = (const float*)d_in[8];
    const float* b2   = (const float*)d_in[9];
    const float* Wr   = (const float*)d_in[10];
    const float* br   = (const float*)d_in[11];
    float* out = (float*)d_out;

    k1_kernel<<<NRELA + 512, 256>>>((const float4*)vew1, (const float4*)vew2,
                                    mvw, m, q, Wr, br);
    bond_kernel<<<N_E / 8, 256>>>(v, e, q, W1, W2, b2, out);
}

// round 11
// speedup vs baseline: 1.2263x; 1.0862x over previous
#include <cuda_runtime.h>
#include <cstdint>

#define N_V   2048
#define N_E   1024
#define N_MOL 64
#define V_DIM 128
#define E_DIM 64
#define H_DIM 32
#define FEAT  (2*V_DIM + E_DIM)   // 320
#define CAP   256                 // per-molecule member capacity (avg 32)

#define RECB  512                 // recover blocks
#define RELB  128                 // rela blocks
#define PVB   64                  // pre-GEMM vertex blocks (av, cv)
#define PEB   32                  // pre-GEMM edge blocks (be)
#define GRID1 (RECB + RELB + PVB + PEB)

// Scratch (static device globals — allocation-free per harness rules)
__device__ int   g_src[N_E];
__device__ int   g_dst[N_E];
__device__ float g_rela[N_V * 3];
__device__ float g_av[N_V * H_DIM];     // A @ v_i   (A = W1[:, 0:128])
__device__ float g_cv[N_V * H_DIM];     // C @ v_i   (C = W1[:, 192:320])
__device__ float g_be[N_E * H_DIM];     // B @ e_er  (B = W1[:, 128:192])

// ---------------------------------------------------------------------------
// Fast accurate softplus: softplus(x) = x/2 + ln2 + ln cosh(x/2).
// |x|<1: 5-term even Taylor of ln cosh (abs err < 4e-7 at boundary) — FMA
// pipe only. Exact path for |x|>=1 (rare; inputs have sigma ~0.13).
// ---------------------------------------------------------------------------
__device__ __forceinline__ float softplus_fast(float x) {
    float ax = fabsf(x);
    if (ax < 1.0f) {
        float t = 0.5f * x;
        float u = t * t;
        float p = 2.1869489e-3f;
        p = fmaf(p, u, -6.7460317e-3f);
        p = fmaf(p, u,  2.2222222e-2f);
        p = fmaf(p, u, -8.3333333e-2f);
        p = fmaf(p, u,  0.5f);
        return fmaf(u, p, t + 0.69314718056f);
    }
    return fmaxf(x, 0.f) + log1pf(__expf(-ax));
}

// ---------------------------------------------------------------------------
// K1: four independent roles, one grid (all co-resident, no interaction).
//   [0,512):   recover src/dst from one-hots (OR fast-path)
//   [512,640): rela forces -> g_rela (single-pass scan compaction)
//   [640,704): av/cv pre-GEMM (vertices)
//   [704,736): be pre-GEMM (edges)
// ---------------------------------------------------------------------------
__global__ void __launch_bounds__(256)
k1_kernel(const uint4* __restrict__ vew1,
          const uint4* __restrict__ vew2,
          const float* __restrict__ mvw,
          const float* __restrict__ m,
          const float* __restrict__ q,
          const float* __restrict__ Wr,
          const float* __restrict__ br,
          const float* __restrict__ v,
          const float* __restrict__ e,
          const float* __restrict__ W1) {
    __shared__ __align__(16) char sbuf[34816];   // 34 KB union buffer
    const int tid  = threadIdx.x;
    const int lane = tid & 31;
    const int wl   = tid >> 5;
    const int bx   = blockIdx.x;

    if (bx < RECB) {
        // ================= recover (OR fast-path) =================
        const int gtid = bx * 256 + tid;                 // [0, 131072)
        uint4 a[4], b[4];
        #pragma unroll
        for (int r = 0; r < 4; r++) a[r] = vew1[r * 131072 + gtid];
        #pragma unroll
        for (int r = 0; r < 4; r++) b[r] = vew2[r * 131072 + gtid];
        #pragma unroll
        for (int r = 0; r < 4; r++) {
            const int idx = r * 131072 + gtid;
            const int i = idx >> 8;                      // vertex (row)
            const int j = (idx & 255) << 2;              // edge base (col)
            if (a[r].x | a[r].y | a[r].z | a[r].w) {     // ~0.2% taken
                if (a[r].x) g_src[j + 0] = i;
                if (a[r].y) g_src[j + 1] = i;
                if (a[r].z) g_src[j + 2] = i;
                if (a[r].w) g_src[j + 3] = i;
            }
            if (b[r].x | b[r].y | b[r].z | b[r].w) {
                if (b[r].x) g_dst[j + 0] = i;
                if (b[r].y) g_dst[j + 1] = i;
                if (b[r].z) g_dst[j + 2] = i;
                if (b[r].w) g_dst[j + 3] = i;
            }
        }
        return;
    }

    if (bx < RECB + RELB) {
        // ================= rela =================
        float* F = (float*)sbuf;
        int*   midx  = (int*)F;          // [0,256)
        float* sqx   = F + 256;
        float* sqy   = F + 512;
        float* sqz   = F + 768;
        float* smm   = F + 1024;
        float* sWr0  = F + 1280;
        float* sWr1  = F + 1312;
        float* sWr2  = F + 1344;
        float* sbr   = F + 1376;
        int*   swsum = (int*)(F + 1408); // 8
        int*   swoff = (int*)(F + 1416); // 8
        int*   ssize = (int*)(F + 1424);

        const int bid = bx - RECB;
        const int mo  = bid >> 1;
        const int par = bid & 1;

        if (tid < H_DIM) {
            sWr0[tid] = Wr[3*tid + 0];
            sWr1[tid] = Wr[3*tid + 1];
            sWr2[tid] = Wr[3*tid + 2];
            sbr[tid]  = br[tid];
        }

        // single-pass scan compaction: thread owns 8 consecutive columns
        const float4* mrow4 = (const float4*)(mvw + mo * N_V);
        float4 v0 = mrow4[2*tid], v1 = mrow4[2*tid + 1];
        unsigned m8 = 0;
        if (v0.x != 0.f) m8 |= 1u;   if (v0.y != 0.f) m8 |= 2u;
        if (v0.z != 0.f) m8 |= 4u;   if (v0.w != 0.f) m8 |= 8u;
        if (v1.x != 0.f) m8 |= 16u;  if (v1.y != 0.f) m8 |= 32u;
        if (v1.z != 0.f) m8 |= 64u;  if (v1.w != 0.f) m8 |= 128u;
        const int c = __popc(m8);
        int incl = c;
        #pragma unroll
        for (int o = 1; o < 32; o <<= 1) {
            int n = __shfl_up_sync(0xffffffffu, incl, o);
            if (lane >= o) incl += n;
        }
        if (lane == 31) swsum[wl] = incl;
        __syncthreads();
        if (tid == 0) {
            int run = 0;
            #pragma unroll
            for (int w8 = 0; w8 < 8; w8++) { swoff[w8] = run; run += swsum[w8]; }
            ssize[0] = run;
        }
        __syncthreads();
        int pos = swoff[wl] + (incl - c);
        #pragma unroll
        for (int k = 0; k < 8; k++) {
            if (m8 & (1u << k)) {
                const int i = tid * 8 + k;
                if (pos < CAP) {
                    midx[pos] = i;
                    sqx[pos] = q[3*i + 0];
                    sqy[pos] = q[3*i + 1];
                    sqz[pos] = q[3*i + 2];
                    smm[pos] = m[i];
                }
                pos++;
            }
        }
        __syncthreads();
        int size = ssize[0];
        if (size > CAP) size = CAP;

        // warp-per-member over this parity half
        for (int s = par + 2 * wl; s < size; s += 16) {
            const float qix = sqx[s], qiy = sqy[s], qiz = sqz[s], mi = smm[s];
            float a0 = 0.f, a1 = 0.f, a2 = 0.f;
            for (int t = lane; t < size; t += 32) {
                float d0 = qix - sqx[t];
                float d1 = qiy - sqy[t];
                float d2 = qiz - sqz[t];
                float n2 = fmaf(d0, d0, fmaf(d1, d1, d2 * d2));
                if (n2 > 0.f) {
                    float ss = 0.f;
                    #pragma unroll
                    for (int h = 0; h < H_DIM; h++) {
                        float x = fmaf(sWr0[h], d0,
                                  fmaf(sWr1[h], d1,
                                  fmaf(sWr2[h], d2, sbr[h])));
                        float sp = softplus_fast(x);
                        ss = fmaf(sp, sp, ss);
                    }
                    float y = rsqrtf(ss);                 // 1/delta_d
                    float cc = (y * y - y) * mi * smm[t] * rsqrtf(n2);
                    a0 = fmaf(d0, cc, a0);
                    a1 = fmaf(d1, cc, a1);
                    a2 = fmaf(d2, cc, a2);
                }
            }
            #pragma unroll
            for (int o = 16; o; o >>= 1) {
                a0 += __shfl_xor_sync(0xffffffffu, a0, o);
                a1 += __shfl_xor_sync(0xffffffffu, a1, o);
                a2 += __shfl_xor_sync(0xffffffffu, a2, o);
            }
            if (lane == 0) {
                const int i = midx[s];        // one writer per vertex
                g_rela[3*i + 0] = a0;
                g_rela[3*i + 1] = a1;
                g_rela[3*i + 2] = a2;
            }
        }
        return;
    }

    if (bx < RECB + RELB + PVB) {
        // ================= pre-GEMM (vertices): av = A@v_i, cv = C@v_i ======
        float* sAT = (float*)sbuf;            // [33*c + t], c<128 (16.9 KB)
        float* sCT = sAT + 33 * V_DIM;        // same shape
        const int b = bx - (RECB + RELB);

        for (int idx = tid; idx < H_DIM * V_DIM; idx += 256) {
            const int cc = idx & 127, t = idx >> 7;      // coalesced W1 rows
            sAT[33*cc + t] = W1[t * FEAT + cc];
            sCT[33*cc + t] = W1[t * FEAT + 192 + cc];
        }
        __syncthreads();

        #pragma unroll
        for (int rnd = 0; rnd < 4; rnd++) {
            const int i = b * 32 + rnd * 8 + wl;         // vertex
            float vr[4];
            #pragma unroll
            for (int k = 0; k < 4; k++) vr[k] = v[i * V_DIM + 32*k + lane];
            float aa = 0.f, cc = 0.f;
            #pragma unroll
            for (int k = 0; k < 4; k++) {
                #pragma unroll
                for (int l = 0; l < 32; l++) {
                    const float vc = __shfl_sync(0xffffffffu, vr[k], l);
                    const int  c2 = 32*k + l;
                    aa = fmaf(vc, sAT[33*c2 + lane], aa);
                    cc = fmaf(vc, sCT[33*c2 + lane], cc);
                }
            }
            g_av[i * H_DIM + lane] = aa;
            g_cv[i * H_DIM + lane] = cc;
        }
        return;
    }

    // ================= pre-GEMM (edges): be = B@e_er =================
    {
        float* sBT = (float*)sbuf;            // [33*c + t], c<64 (8.4 KB)
        const int b = bx - (RECB + RELB + PVB);

        for (int idx = tid; idx < H_DIM * E_DIM; idx += 256) {
            const int cc = idx & 63, t = idx >> 6;       // coalesced W1 rows
            sBT[33*cc + t] = W1[t * FEAT + V_DIM + cc];
        }
        __syncthreads();

        #pragma unroll
        for (int rnd = 0; rnd < 4; rnd++) {
            const int er = b * 32 + rnd * 8 + wl;        // edge
            float er0 = e[er * E_DIM + lane];
            float er1 = e[er * E_DIM + 32 + lane];
            float bb = 0.f;
            #pragma unroll
            for (int l = 0; l < 32; l++) {
                const float c0 = __shfl_sync(0xffffffffu, er0, l);
                const float c1 = __shfl_sync(0xffffffffu, er1, l);
                bb = fmaf(c0, sBT[33*l + lane], bb);
                bb = fmaf(c1, sBT[33*(32 + l) + lane], bb);
            }
            g_be[er * H_DIM + lane] = bb;
        }
    }
}

// ---------------------------------------------------------------------------
// K2: bond combine. One warp per edge er; lane = hidden unit.
// h_fwd = relu(av[u] + be[er] + cv[w]);  h_rev = relu(av[w] + be[er] + cv[u])
// val = W2·h + b2;  out rows er and er+N_E = unit_dq * val + g_rela.
// ---------------------------------------------------------------------------
__global__ void __launch_bounds__(256)
bond_kernel(const float* __restrict__ q,
            const float* __restrict__ W2,
            const float* __restrict__ b2,
            float* __restrict__ out) {
    const int tid  = threadIdx.x;
    const int lane = tid & 31;
    const int wl   = tid >> 5;
    const int er   = blockIdx.x * 8 + wl;     // 128 blocks * 8 = 1024 edges
    const int u = g_src[er];
    const int w = g_dst[er];

    const float au = g_av[u * H_DIM + lane];
    const float aw = g_av[w * H_DIM + lane];
    const float cu = g_cv[u * H_DIM + lane];
    const float cw = g_cv[w * H_DIM + lane];
    const float bb = g_be[er * H_DIM + lane];
    const float w2l = W2[lane];

    float vf = fmaxf(au + bb + cw, 0.f) * w2l;
    float vr = fmaxf(aw + bb + cu, 0.f) * w2l;
    #pragma unroll
    for (int o = 16; o; o >>= 1) {
        vf += __shfl_xor_sync(0xffffffffu, vf, o);
        vr += __shfl_xor_sync(0xffffffffu, vr, o);
    }

    if (lane == 0) {
        const float bias = b2[0];
        vf += bias;
        vr += bias;
        float d0 = q[3*u + 0] - q[3*w + 0];
        float d1 = q[3*u + 1] - q[3*w + 1];
        float d2 = q[3*u + 2] - q[3*w + 2];
        float inv = rsqrtf(fmaf(d0, d0, fmaf(d1, d1, d2 * d2)));
        float sf = inv * vf;
        float sr = inv * vr;
        const int kf = er;               // row using dq = q[u]-q[w]
        const int kr = er + N_E;         // row using dq = q[w]-q[u]
        out[3*kf + 0] = fmaf(d0,  sf, g_rela[3*kf + 0]);
        out[3*kf + 1] = fmaf(d1,  sf, g_rela[3*kf + 1]);
        out[3*kf + 2] = fmaf(d2,  sf, g_rela[3*kf + 2]);
        out[3*kr + 0] = fmaf(-d0, sr, g_rela[3*kr + 0]);
        out[3*kr + 1] = fmaf(-d1, sr, g_rela[3*kr + 1]);
        out[3*kr + 2] = fmaf(-d2, sr, g_rela[3*kr + 2]);
    }
}

// ---------------------------------------------------------------------------
extern "C" void kernel_launch(void* const* d_in, const int* in_sizes, int n_in,
                              void* d_out, int out_size) {
    const float* v    = (const float*)d_in[0];
    const float* e    = (const float*)d_in[1];
    const float* m    = (const float*)d_in[2];
    const float* q    = (const float*)d_in[3];
    const float* vew1 = (const float*)d_in[4];
    const float* vew2 = (const float*)d_in[5];
    const float* mvw  = (const float*)d_in[6];
    const float* W1   = (const float*)d_in[7];
    const float* W2   = (const float*)d_in[8];
    const float* b2   = (const float*)d_in[9];
    const float* Wr   = (const float*)d_in[10];
    const float* br   = (const float*)d_in[11];
    float* out = (float*)d_out;

    k1_kernel<<<GRID1, 256>>>((const uint4*)vew1, (const uint4*)vew2,
                              mvw, m, q, Wr, br, v, e, W1);
    bond_kernel<<<N_E / 8, 256>>>(q, W2, b2, out);
}

// round 12
// speedup vs baseline: 1.2832x; 1.0464x over previous
#include <cuda_runtime.h>
#include <cstdint>

#define N_V   2048
#define N_E   1024
#define N_MOL 64
#define V_DIM 128
#define E_DIM 64
#define H_DIM 32
#define FEAT  (2*V_DIM + E_DIM)   // 320
#define CAP   256                 // per-molecule member capacity (avg 32)

#define RECB  512                 // recover blocks
#define RELB  128                 // rela blocks
#define PVB   64                  // pre-GEMM vertex blocks (av, cv)
#define PEB   32                  // pre-GEMM edge blocks (be)
#define GRID1 (RECB + RELB + PVB + PEB)

// Scratch (static device globals — allocation-free per harness rules)
__device__ int   g_src[N_E];
__device__ int   g_dst[N_E];
__device__ float g_rela[N_V * 3];
__device__ float g_av[N_V * H_DIM];     // A @ v_i   (A = W1[:, 0:128])
__device__ float g_cv[N_V * H_DIM];     // C @ v_i   (C = W1[:, 192:320])
__device__ float g_be[N_E * H_DIM];     // B @ e_er  (B = W1[:, 128:192])

// ---------------------------------------------------------------------------
// Fast accurate softplus: softplus(x) = x/2 + ln2 + ln cosh(x/2).
// |x|<1: 5-term even Taylor of ln cosh (abs err < 4e-7 at boundary) — FMA
// pipe only. Exact path for |x|>=1 (rare; inputs have sigma ~0.13).
// ---------------------------------------------------------------------------
__device__ __forceinline__ float softplus_fast(float x) {
    float ax = fabsf(x);
    if (ax < 1.0f) {
        float t = 0.5f * x;
        float u = t * t;
        float p = 2.1869489e-3f;
        p = fmaf(p, u, -6.7460317e-3f);
        p = fmaf(p, u,  2.2222222e-2f);
        p = fmaf(p, u, -8.3333333e-2f);
        p = fmaf(p, u,  0.5f);
        return fmaf(u, p, t + 0.69314718056f);
    }
    return fmaxf(x, 0.f) + log1pf(__expf(-ax));
}

// ---------------------------------------------------------------------------
// K1: four independent roles, one grid (all co-resident, no interaction).
//   [0,512):   recover src/dst from one-hots (OR fast-path)
//   [512,640): rela forces -> g_rela (single-pass scan compaction)
//   [640,704): av/cv pre-GEMM (vertices)
//   [704,736): be pre-GEMM (edges)
// ---------------------------------------------------------------------------
__global__ void __launch_bounds__(256)
k1_kernel(const uint4* __restrict__ vew1,
          const uint4* __restrict__ vew2,
          const float* __restrict__ mvw,
          const float* __restrict__ m,
          const float* __restrict__ q,
          const float* __restrict__ Wr,
          const float* __restrict__ br,
          const float* __restrict__ v,
          const float* __restrict__ e,
          const float* __restrict__ W1) {
    __shared__ __align__(16) char sbuf[34816];   // 34 KB union buffer
    const int tid  = threadIdx.x;
    const int lane = tid & 31;
    const int wl   = tid >> 5;
    const int bx   = blockIdx.x;

    if (bx < RECB) {
        // ================= recover (OR fast-path) =================
        const int gtid = bx * 256 + tid;                 // [0, 131072)
        uint4 a[4], b[4];
        #pragma unroll
        for (int r = 0; r < 4; r++) a[r] = vew1[r * 131072 + gtid];
        #pragma unroll
        for (int r = 0; r < 4; r++) b[r] = vew2[r * 131072 + gtid];
        #pragma unroll
        for (int r = 0; r < 4; r++) {
            const int idx = r * 131072 + gtid;
            const int i = idx >> 8;                      // vertex (row)
            const int j = (idx & 255) << 2;              // edge base (col)
            if (a[r].x | a[r].y | a[r].z | a[r].w) {     // ~0.2% taken
                if (a[r].x) g_src[j + 0] = i;
                if (a[r].y) g_src[j + 1] = i;
                if (a[r].z) g_src[j + 2] = i;
                if (a[r].w) g_src[j + 3] = i;
            }
            if (b[r].x | b[r].y | b[r].z | b[r].w) {
                if (b[r].x) g_dst[j + 0] = i;
                if (b[r].y) g_dst[j + 1] = i;
                if (b[r].z) g_dst[j + 2] = i;
                if (b[r].w) g_dst[j + 3] = i;
            }
        }
        return;
    }

    if (bx < RECB + RELB) {
        // ================= rela =================
        float* F = (float*)sbuf;
        int*   midx  = (int*)F;          // [0,256)
        float* sqx   = F + 256;
        float* sqy   = F + 512;
        float* sqz   = F + 768;
        float* smm   = F + 1024;
        float* sWr0  = F + 1280;
        float* sWr1  = F + 1312;
        float* sWr2  = F + 1344;
        float* sbr   = F + 1376;
        int*   swsum = (int*)(F + 1408); // 8
        int*   swoff = (int*)(F + 1416); // 8
        int*   ssize = (int*)(F + 1424);

        const int bid = bx - RECB;
        const int mo  = bid >> 1;
        const int par = bid & 1;

        if (tid < H_DIM) {
            sWr0[tid] = Wr[3*tid + 0];
            sWr1[tid] = Wr[3*tid + 1];
            sWr2[tid] = Wr[3*tid + 2];
            sbr[tid]  = br[tid];
        }

        // single-pass scan compaction: thread owns 8 consecutive columns
        const float4* mrow4 = (const float4*)(mvw + mo * N_V);
        float4 v0 = mrow4[2*tid], v1 = mrow4[2*tid + 1];
        unsigned m8 = 0;
        if (v0.x != 0.f) m8 |= 1u;   if (v0.y != 0.f) m8 |= 2u;
        if (v0.z != 0.f) m8 |= 4u;   if (v0.w != 0.f) m8 |= 8u;
        if (v1.x != 0.f) m8 |= 16u;  if (v1.y != 0.f) m8 |= 32u;
        if (v1.z != 0.f) m8 |= 64u;  if (v1.w != 0.f) m8 |= 128u;
        const int c = __popc(m8);
        int incl = c;
        #pragma unroll
        for (int o = 1; o < 32; o <<= 1) {
            int n = __shfl_up_sync(0xffffffffu, incl, o);
            if (lane >= o) incl += n;
        }
        if (lane == 31) swsum[wl] = incl;
        __syncthreads();
        if (tid == 0) {
            int run = 0;
            #pragma unroll
            for (int w8 = 0; w8 < 8; w8++) { swoff[w8] = run; run += swsum[w8]; }
            ssize[0] = run;
        }
        __syncthreads();
        int pos = swoff[wl] + (incl - c);
        #pragma unroll
        for (int k = 0; k < 8; k++) {
            if (m8 & (1u << k)) {
                const int i = tid * 8 + k;
                if (pos < CAP) {
                    midx[pos] = i;
                    sqx[pos] = q[3*i + 0];
                    sqy[pos] = q[3*i + 1];
                    sqz[pos] = q[3*i + 2];
                    smm[pos] = m[i];
                }
                pos++;
            }
        }
        __syncthreads();
        int size = ssize[0];
        if (size > CAP) size = CAP;

        // warp-per-member over this parity half
        for (int s = par + 2 * wl; s < size; s += 16) {
            const float qix = sqx[s], qiy = sqy[s], qiz = sqz[s], mi = smm[s];
            float a0 = 0.f, a1 = 0.f, a2 = 0.f;
            for (int t = lane; t < size; t += 32) {
                float d0 = qix - sqx[t];
                float d1 = qiy - sqy[t];
                float d2 = qiz - sqz[t];
                float n2 = fmaf(d0, d0, fmaf(d1, d1, d2 * d2));
                if (n2 > 0.f) {
                    float ss = 0.f;
                    #pragma unroll
                    for (int h = 0; h < H_DIM; h++) {
                        float x = fmaf(sWr0[h], d0,
                                  fmaf(sWr1[h], d1,
                                  fmaf(sWr2[h], d2, sbr[h])));
                        float sp = softplus_fast(x);
                        ss = fmaf(sp, sp, ss);
                    }
                    float y = rsqrtf(ss);                 // 1/delta_d
                    float cc = (y * y - y) * mi * smm[t] * rsqrtf(n2);
                    a0 = fmaf(d0, cc, a0);
                    a1 = fmaf(d1, cc, a1);
                    a2 = fmaf(d2, cc, a2);
                }
            }
            #pragma unroll
            for (int o = 16; o; o >>= 1) {
                a0 += __shfl_xor_sync(0xffffffffu, a0, o);
                a1 += __shfl_xor_sync(0xffffffffu, a1, o);
                a2 += __shfl_xor_sync(0xffffffffu, a2, o);
            }
            if (lane == 0) {
                const int i = midx[s];        // one writer per vertex
                g_rela[3*i + 0] = a0;
                g_rela[3*i + 1] = a1;
                g_rela[3*i + 2] = a2;
            }
        }
        return;
    }

    if (bx < RECB + RELB + PVB) {
        // ================= pre-GEMM (vertices): av = A@v_i, cv = C@v_i ======
        float* sAT = (float*)sbuf;            // [33*c + t], c<128 (16.9 KB)
        float* sCT = sAT + 33 * V_DIM;        // same shape
        const int b = bx - (RECB + RELB);

        for (int idx = tid; idx < H_DIM * V_DIM; idx += 256) {
            const int cc = idx & 127, t = idx >> 7;      // coalesced W1 rows
            sAT[33*cc + t] = W1[t * FEAT + cc];
            sCT[33*cc + t] = W1[t * FEAT + 192 + cc];
        }
        __syncthreads();

        #pragma unroll
        for (int rnd = 0; rnd < 4; rnd++) {
            const int i = b * 32 + rnd * 8 + wl;         // vertex
            float vr[4];
            #pragma unroll
            for (int k = 0; k < 4; k++) vr[k] = v[i * V_DIM + 32*k + lane];
            float aa = 0.f, cc = 0.f;
            #pragma unroll
            for (int k = 0; k < 4; k++) {
                #pragma unroll
                for (int l = 0; l < 32; l++) {
                    const float vc = __shfl_sync(0xffffffffu, vr[k], l);
                    const int  c2 = 32*k + l;
                    aa = fmaf(vc, sAT[33*c2 + lane], aa);
                    cc = fmaf(vc, sCT[33*c2 + lane], cc);
                }
            }
            g_av[i * H_DIM + lane] = aa;
            g_cv[i * H_DIM + lane] = cc;
        }
        return;
    }

    // ================= pre-GEMM (edges): be = B@e_er =================
    {
        float* sBT = (float*)sbuf;            // [33*c + t], c<64 (8.4 KB)
        const int b = bx - (RECB + RELB + PVB);

        for (int idx = tid; idx < H_DIM * E_DIM; idx += 256) {
            const int cc = idx & 63, t = idx >> 6;       // coalesced W1 rows
            sBT[33*cc + t] = W1[t * FEAT + V_DIM + cc];
        }
        __syncthreads();

        #pragma unroll
        for (int rnd = 0; rnd < 4; rnd++) {
            const int er = b * 32 + rnd * 8 + wl;        // edge
            float er0 = e[er * E_DIM + lane];
            float er1 = e[er * E_DIM + 32 + lane];
            float bb = 0.f;
            #pragma unroll
            for (int l = 0; l < 32; l++) {
                const float c0 = __shfl_sync(0xffffffffu, er0, l);
                const float c1 = __shfl_sync(0xffffffffu, er1, l);
                bb = fmaf(c0, sBT[33*l + lane], bb);
                bb = fmaf(c1, sBT[33*(32 + l) + lane], bb);
            }
            g_be[er * H_DIM + lane] = bb;
        }
    }
}

// ---------------------------------------------------------------------------
// K2: bond combine, latency-optimized. One warp per TWO edges (er0, er1).
// All index-independent loads (be, W2, b2, g_rela rows) are issued before the
// g_src/g_dst hop, so the dependent chain is 2 memory hops. Epilogue runs on
// lanes 0 and 1 concurrently (one edge each).
// ---------------------------------------------------------------------------
__global__ void __launch_bounds__(128)
bond_kernel(const float* __restrict__ q,
            const float* __restrict__ W2,
            const float* __restrict__ b2,
            float* __restrict__ out) {
    const int lane = threadIdx.x & 31;
    const int warp = (blockIdx.x * 128 + threadIdx.x) >> 5;  // [0, 512)
    const int er0 = warp * 2;
    const int er1 = er0 + 1;

    // ---- independent loads first (no index dependency) ----
    const float be0 = g_be[er0 * H_DIM + lane];
    const float be1 = g_be[er1 * H_DIM + lane];
    const float w2l = W2[lane];
    const float bias = b2[0];
    // g_rela rows for all 4 output rows (broadcast scalar loads)
    const float rf0x = g_rela[3*er0 + 0], rf0y = g_rela[3*er0 + 1], rf0z = g_rela[3*er0 + 2];
    const float rf1x = g_rela[3*er1 + 0], rf1y = g_rela[3*er1 + 1], rf1z = g_rela[3*er1 + 2];
    const int kr0 = er0 + N_E, kr1 = er1 + N_E;
    const float rr0x = g_rela[3*kr0 + 0], rr0y = g_rela[3*kr0 + 1], rr0z = g_rela[3*kr0 + 2];
    const float rr1x = g_rela[3*kr1 + 0], rr1y = g_rela[3*kr1 + 1], rr1z = g_rela[3*kr1 + 2];

    // ---- hop 1: indices ----
    const int u0 = g_src[er0], w0 = g_dst[er0];
    const int u1 = g_src[er1], w1 = g_dst[er1];

    // ---- hop 2: per-vertex MLP partials + positions (all independent) ----
    const float au0 = g_av[u0 * H_DIM + lane];
    const float cw0 = g_cv[w0 * H_DIM + lane];
    const float aw0 = g_av[w0 * H_DIM + lane];
    const float cu0 = g_cv[u0 * H_DIM + lane];
    const float au1 = g_av[u1 * H_DIM + lane];
    const float cw1 = g_cv[w1 * H_DIM + lane];
    const float aw1 = g_av[w1 * H_DIM + lane];
    const float cu1 = g_cv[u1 * H_DIM + lane];
    const float qu0x = q[3*u0 + 0], qu0y = q[3*u0 + 1], qu0z = q[3*u0 + 2];
    const float qw0x = q[3*w0 + 0], qw0y = q[3*w0 + 1], qw0z = q[3*w0 + 2];
    const float qu1x = q[3*u1 + 0], qu1y = q[3*u1 + 1], qu1z = q[3*u1 + 2];
    const float qw1x = q[3*w1 + 0], qw1y = q[3*w1 + 1], qw1z = q[3*w1 + 2];

    // ---- hidden layer + W2 dot (4 reductions interleaved) ----
    float vf0 = fmaxf(au0 + be0 + cw0, 0.f) * w2l;
    float vr0 = fmaxf(aw0 + be0 + cu0, 0.f) * w2l;
    float vf1 = fmaxf(au1 + be1 + cw1, 0.f) * w2l;
    float vr1 = fmaxf(aw1 + be1 + cu1, 0.f) * w2l;
    #pragma unroll
    for (int o = 16; o; o >>= 1) {
        vf0 += __shfl_xor_sync(0xffffffffu, vf0, o);
        vr0 += __shfl_xor_sync(0xffffffffu, vr0, o);
        vf1 += __shfl_xor_sync(0xffffffffu, vf1, o);
        vr1 += __shfl_xor_sync(0xffffffffu, vr1, o);
    }

    // ---- epilogue: lane 0 -> er0, lane 1 -> er1 (concurrent) ----
    if (lane < 2) {
        const bool second = (lane == 1);
        const int   er = second ? er1 : er0;
        const int   kr = second ? kr1 : kr0;
        const float vf = (second ? vf1 : vf0) + bias;
        const float vr = (second ? vr1 : vr0) + bias;
        const float d0 = (second ? qu1x : qu0x) - (second ? qw1x : qw0x);
        const float d1 = (second ? qu1y : qu0y) - (second ? qw1y : qw0y);
        const float d2 = (second ? qu1z : qu0z) - (second ? qw1z : qw0z);
        const float inv = rsqrtf(fmaf(d0, d0, fmaf(d1, d1, d2 * d2)));
        const float sf = inv * vf;
        const float sr = inv * vr;
        out[3*er + 0] = fmaf(d0,  sf, second ? rf1x : rf0x);
        out[3*er + 1] = fmaf(d1,  sf, second ? rf1y : rf0y);
        out[3*er + 2] = fmaf(d2,  sf, second ? rf1z : rf0z);
        out[3*kr + 0] = fmaf(-d0, sr, second ? rr1x : rr0x);
        out[3*kr + 1] = fmaf(-d1, sr, second ? rr1y : rr0y);
        out[3*kr + 2] = fmaf(-d2, sr, second ? rr1z : rr0z);
    }
}

// ---------------------------------------------------------------------------
extern "C" void kernel_launch(void* const* d_in, const int* in_sizes, int n_in,
                              void* d_out, int out_size) {
    const float* v    = (const float*)d_in[0];
    const float* e    = (const float*)d_in[1];
    const float* m    = (const float*)d_in[2];
    const float* q    = (const float*)d_in[3];
    const float* vew1 = (const float*)d_in[4];
    const float* vew2 = (const float*)d_in[5];
    const float* mvw  = (const float*)d_in[6];
    const float* W1   = (const float*)d_in[7];
    const float* W2   = (const float*)d_in[8];
    const float* b2   = (const float*)d_in[9];
    const float* Wr   = (const float*)d_in[10];
    const float* br   = (const float*)d_in[11];
    float* out = (float*)d_out;

    k1_kernel<<<GRID1, 256>>>((const uint4*)vew1, (const uint4*)vew2,
                              mvw, m, q, Wr, br, v, e, W1);
    bond_kernel<<<N_E / 8, 128>>>(q, W2, b2, out);
}